// round 15
// baseline (speedup 1.0000x reference)
#include <cuda_runtime.h>
#include <cstdint>

#define M_SLOTS 10
#define HW      7744          // 88*88
#define HWV     1936          // HW in 16B units
#define ROWS    8192          // B*C
#define QL      484           // j-quarter length in 16B units (1936/4)
#define RPB     4             // rows per block (shared by all 4 warps)
#define NT      128           // 4 warps, each owns one j-quarter of the 4 rows
#define DEPTH   4             // cp.async ring depth
#define ITERS   16            // ceil(484/32)

typedef unsigned long long u64;

__device__ __forceinline__ u64 fma2(u64 a, u64 b, u64 c) {
    u64 d;
    asm("fma.rn.f32x2 %0, %1, %2, %3;" : "=l"(d) : "l"(a), "l"(b), "l"(c));
    return d;
}
__device__ __forceinline__ u64 pack2(float lo, float hi) {
    u64 t;
    asm("mov.b64 %0, {%1, %2};" : "=l"(t) : "f"(lo), "f"(hi));
    return t;
}
__device__ __forceinline__ float hsum2(u64 a) {
    float x, y;
    asm("mov.b64 {%0, %1}, %2;" : "=f"(x), "=f"(y) : "l"(a));
    return x + y;
}
__device__ __forceinline__ u64 d2u(double d) { return (u64)__double_as_longlong(d); }
__device__ __forceinline__ double u2d(u64 v) { return __longlong_as_double((long long)v); }

__device__ __forceinline__ uint32_t smem_u32(const void* p) {
    uint32_t a;
    asm("{ .reg .u64 t; cvta.to.shared.u64 t, %1; cvt.u32.u64 %0, t; }" : "=r"(a) : "l"(p));
    return a;
}
__device__ __forceinline__ void cp16(uint32_t dst, const void* src) {
    asm volatile("cp.async.cg.shared.global [%0], [%1], 16;" :: "r"(dst), "l"(src) : "memory");
}
__device__ __forceinline__ void cp_commit() {
    asm volatile("cp.async.commit_group;" ::: "memory");
}
__device__ __forceinline__ void cp_wait3() {
    asm volatile("cp.async.wait_group 3;" ::: "memory");
}

__global__ __launch_bounds__(NT, 4)
void memaug_fused(const float* __restrict__ x,
                  const float* __restrict__ mem,
                  float* __restrict__ out) {
    __shared__ double2 xs[4][DEPTH][RPB][32];   // 32 KB per-warp cp.async rings
    __shared__ float p_part[4][RPB][M_SLOTS];
    __shared__ float p_fin[RPB][M_SLOTS];

    const int tid  = threadIdx.x;
    const int lane = tid & 31;
    const int warp = tid >> 5;          // j-quarter index 0..3
    const int row0 = blockIdx.x * RPB;

    const double2* __restrict__ mw  = (const double2*)mem;
    const double2* __restrict__ xr0 = (const double2*)(x + (size_t)(row0 + 0) * HW) + warp * QL;
    const double2* __restrict__ xr1 = (const double2*)(x + (size_t)(row0 + 1) * HW) + warp * QL;
    const double2* __restrict__ xr2 = (const double2*)(x + (size_t)(row0 + 2) * HW) + warp * QL;
    const double2* __restrict__ xr3 = (const double2*)(x + (size_t)(row0 + 3) * HW) + warp * QL;

    const uint32_t sbase = smem_u32(&xs[warp][0][0][0]);   // this warp's ring

    // issue cp.async group for iteration s (may be empty -> still commits)
    auto issue = [&](int s) {
        if (s < ITERS) {
            const int joff = s * 32 + lane;
            if (joff < QL) {
                const uint32_t st = (uint32_t)(s & (DEPTH - 1));
                const uint32_t d0 = sbase + ((st * RPB + 0) * 32 + lane) * 16;
                const uint32_t d1 = sbase + ((st * RPB + 1) * 32 + lane) * 16;
                const uint32_t d2 = sbase + ((st * RPB + 2) * 32 + lane) * 16;
                const uint32_t d3 = sbase + ((st * RPB + 3) * 32 + lane) * 16;
                cp16(d0, xr0 + joff);
                cp16(d1, xr1 + joff);
                cp16(d2, xr2 + joff);
                cp16(d3, xr3 + joff);
            }
        }
        cp_commit();
    };

    // ------------- Phase 1: HW-dim packed f32x2 partial scores -------------
    u64 acc[RPB][M_SLOTS];
    #pragma unroll
    for (int r = 0; r < RPB; r++)
        #pragma unroll
        for (int m = 0; m < M_SLOTS; m++) acc[r][m] = 0ull;

    issue(0); issue(1); issue(2);

    for (int it = 0; it < ITERS; it++) {
        issue(it + DEPTH - 1);
        cp_wait3();

        const int joff = it * 32 + lane;
        if (joff < QL) {
            const int st = it & (DEPTH - 1);
            double2 xd0 = xs[warp][st][0][lane];
            double2 xd1 = xs[warp][st][1][lane];
            double2 xd2 = xs[warp][st][2][lane];
            double2 xd3 = xs[warp][st][3][lane];
            const u64 x0a = d2u(xd0.x), x0b = d2u(xd0.y);
            const u64 x1a = d2u(xd1.x), x1b = d2u(xd1.y);
            const u64 x2a = d2u(xd2.x), x2b = d2u(xd2.y);
            const u64 x3a = d2u(xd3.x), x3b = d2u(xd3.y);
            const int j = warp * QL + joff;
            #pragma unroll
            for (int m = 0; m < M_SLOTS; m++) {
                double2 wd = __ldg(&mw[(size_t)m * HWV + j]);
                const u64 wa = d2u(wd.x), wb = d2u(wd.y);
                acc[0][m] = fma2(x0a, wa, acc[0][m]);
                acc[1][m] = fma2(x1a, wa, acc[1][m]);
                acc[2][m] = fma2(x2a, wa, acc[2][m]);
                acc[3][m] = fma2(x3a, wa, acc[3][m]);
                acc[0][m] = fma2(x0b, wb, acc[0][m]);
                acc[1][m] = fma2(x1b, wb, acc[1][m]);
                acc[2][m] = fma2(x2b, wb, acc[2][m]);
                acc[3][m] = fma2(x3b, wb, acc[3][m]);
            }
        }
    }

    // reduce packed pairs + warp tree -> p_part[warp]
    #pragma unroll
    for (int r = 0; r < RPB; r++) {
        #pragma unroll
        for (int m = 0; m < M_SLOTS; m++) {
            float v = hsum2(acc[r][m]);
            #pragma unroll
            for (int k = 16; k > 0; k >>= 1)
                v += __shfl_xor_sync(0xFFFFFFFFu, v, k);
            if (lane == 0) p_part[warp][r][m] = v;
        }
    }
    __syncthreads();

    // softmax: one thread per row
    if (tid < RPB) {
        float s[M_SLOTS];
        float mx = -1e30f;
        #pragma unroll
        for (int m = 0; m < M_SLOTS; m++) {
            s[m] = p_part[0][tid][m] + p_part[1][tid][m]
                 + p_part[2][tid][m] + p_part[3][tid][m];
            mx = fmaxf(mx, s[m]);
        }
        float sum = 0.0f;
        #pragma unroll
        for (int m = 0; m < M_SLOTS; m++) { s[m] = __expf(s[m] - mx); sum += s[m]; }
        float inv = 1.0f / sum;
        #pragma unroll
        for (int m = 0; m < M_SLOTS; m++) p_fin[tid][m] = s[m] * inv;
    }
    __syncthreads();

    // ------------- Phase 2: value, HW-dim packed f32x2 ---------------------
    u64 q[RPB][M_SLOTS];
    #pragma unroll
    for (int r = 0; r < RPB; r++)
        #pragma unroll
        for (int m = 0; m < M_SLOTS; m++) {
            float pv = p_fin[r][m];
            q[r][m] = pack2(pv, pv);
        }

    double2* __restrict__ o0 = (double2*)(out + (size_t)(row0 + 0) * HW) + warp * QL;
    double2* __restrict__ o1 = (double2*)(out + (size_t)(row0 + 1) * HW) + warp * QL;
    double2* __restrict__ o2 = (double2*)(out + (size_t)(row0 + 2) * HW) + warp * QL;
    double2* __restrict__ o3 = (double2*)(out + (size_t)(row0 + 3) * HW) + warp * QL;

    for (int joff = lane; joff < QL; joff += 32) {
        const int j = warp * QL + joff;
        u64 a0a = 0ull, a0b = 0ull, a1a = 0ull, a1b = 0ull;
        u64 a2a = 0ull, a2b = 0ull, a3a = 0ull, a3b = 0ull;
        #pragma unroll
        for (int m = 0; m < M_SLOTS; m++) {
            double2 wd = __ldg(&mw[(size_t)m * HWV + j]);
            const u64 wa = d2u(wd.x), wb = d2u(wd.y);
            a0a = fma2(q[0][m], wa, a0a);  a0b = fma2(q[0][m], wb, a0b);
            a1a = fma2(q[1][m], wa, a1a);  a1b = fma2(q[1][m], wb, a1b);
            a2a = fma2(q[2][m], wa, a2a);  a2b = fma2(q[2][m], wb, a2b);
            a3a = fma2(q[3][m], wa, a3a);  a3b = fma2(q[3][m], wb, a3b);
        }
        double2 v0, v1, v2, v3;
        v0.x = u2d(a0a); v0.y = u2d(a0b);
        v1.x = u2d(a1a); v1.y = u2d(a1b);
        v2.x = u2d(a2a); v2.y = u2d(a2b);
        v3.x = u2d(a3a); v3.y = u2d(a3b);
        __stcs(o0 + joff, v0);
        __stcs(o1 + joff, v1);
        __stcs(o2 + joff, v2);
        __stcs(o3 + joff, v3);
    }
}

extern "C" void kernel_launch(void* const* d_in, const int* in_sizes, int n_in,
                              void* d_out, int out_size) {
    const float* x   = (const float*)d_in[0];   // [32,256,88,88]
    const float* mem = (const float*)d_in[1];   // [10,88,88]
    float* out = (float*)d_out;

    dim3 grid(ROWS / RPB);    // 2048 blocks
    memaug_fused<<<grid, NT>>>(x, mem, out);
}

// round 16
// speedup vs baseline: 1.1208x; 1.1208x over previous
#include <cuda_runtime.h>
#include <cstdint>

#define M_SLOTS 10
#define MS_HALF 5
#define HW      7744          // 88*88
#define HWV     1936          // HW in 16B units
#define ROWS    8192          // B*C
#define HL      968           // j-half length in 16B units (1936/2)
#define QL      484           // j-quarter length in 16B units
#define RPB     4             // rows per block (shared by all 4 warps)
#define NT      128

typedef unsigned long long u64;

__device__ __forceinline__ u64 fma2(u64 a, u64 b, u64 c) {
    u64 d;
    asm("fma.rn.f32x2 %0, %1, %2, %3;" : "=l"(d) : "l"(a), "l"(b), "l"(c));
    return d;
}
__device__ __forceinline__ u64 pack2(float lo, float hi) {
    u64 t;
    asm("mov.b64 %0, {%1, %2};" : "=l"(t) : "f"(lo), "f"(hi));
    return t;
}
__device__ __forceinline__ float hsum2(u64 a) {
    float x, y;
    asm("mov.b64 {%0, %1}, %2;" : "=f"(x), "=f"(y) : "l"(a));
    return x + y;
}
__device__ __forceinline__ u64 d2u(double d) { return (u64)__double_as_longlong(d); }
__device__ __forceinline__ double u2d(u64 v) { return __longlong_as_double((long long)v); }

__global__ __launch_bounds__(NT, 4)
void memaug_fused(const float* __restrict__ x,
                  const float* __restrict__ mem,
                  float* __restrict__ out) {
    __shared__ float p_part[4][RPB][MS_HALF];   // [warp][row][slot-within-group]
    __shared__ float p_fin[RPB][M_SLOTS];

    const int tid  = threadIdx.x;
    const int lane = tid & 31;
    const int warp = tid >> 5;
    const int half = warp >> 1;         // j-half 0..1
    const int sgrp = warp & 1;          // slot group: slots [sgrp*5, sgrp*5+5)
    const int row0 = blockIdx.x * RPB;

    const double2* __restrict__ mw  = (const double2*)mem;
    const double2* __restrict__ xr0 = (const double2*)(x + (size_t)(row0 + 0) * HW);
    const double2* __restrict__ xr1 = (const double2*)(x + (size_t)(row0 + 1) * HW);
    const double2* __restrict__ xr2 = (const double2*)(x + (size_t)(row0 + 2) * HW);
    const double2* __restrict__ xr3 = (const double2*)(x + (size_t)(row0 + 3) * HW);

    // ------------- Phase 1: 4 rows x 5 slots per warp, j-half, prefetch ----
    {
        const int jbeg = half * HL + lane;
        const int jend = half * HL + HL;
        const size_t mbase = (size_t)(sgrp * MS_HALF) * HWV;

        u64 acc[RPB][MS_HALF];
        #pragma unroll
        for (int r = 0; r < RPB; r++)
            #pragma unroll
            for (int m = 0; m < MS_HALF; m++) acc[r][m] = 0ull;

        int j = jbeg;
        double2 za = {0.0, 0.0};
        double2 xa0 = za, xa1 = za, xa2 = za, xa3 = za;
        if (j < jend) {
            xa0 = __ldcs(xr0 + j); xa1 = __ldcs(xr1 + j);
            xa2 = __ldcs(xr2 + j); xa3 = __ldcs(xr3 + j);
        }
        while (j < jend) {
            const int jn = j + 32;
            double2 xb0 = za, xb1 = za, xb2 = za, xb3 = za;
            if (jn < jend) {
                xb0 = __ldcs(xr0 + jn); xb1 = __ldcs(xr1 + jn);
                xb2 = __ldcs(xr2 + jn); xb3 = __ldcs(xr3 + jn);
            }
            const u64 x0a = d2u(xa0.x), x0b = d2u(xa0.y);
            const u64 x1a = d2u(xa1.x), x1b = d2u(xa1.y);
            const u64 x2a = d2u(xa2.x), x2b = d2u(xa2.y);
            const u64 x3a = d2u(xa3.x), x3b = d2u(xa3.y);
            #pragma unroll
            for (int m = 0; m < MS_HALF; m++) {
                double2 wd = __ldg(&mw[mbase + (size_t)m * HWV + j]);
                const u64 wa = d2u(wd.x), wb = d2u(wd.y);
                acc[0][m] = fma2(x0a, wa, acc[0][m]);
                acc[1][m] = fma2(x1a, wa, acc[1][m]);
                acc[2][m] = fma2(x2a, wa, acc[2][m]);
                acc[3][m] = fma2(x3a, wa, acc[3][m]);
                acc[0][m] = fma2(x0b, wb, acc[0][m]);
                acc[1][m] = fma2(x1b, wb, acc[1][m]);
                acc[2][m] = fma2(x2b, wb, acc[2][m]);
                acc[3][m] = fma2(x3b, wb, acc[3][m]);
            }
            xa0 = xb0; xa1 = xb1; xa2 = xb2; xa3 = xb3;
            j = jn;
        }

        // warp reduce -> p_part[warp]
        #pragma unroll
        for (int r = 0; r < RPB; r++) {
            #pragma unroll
            for (int m = 0; m < MS_HALF; m++) {
                float v = hsum2(acc[r][m]);
                #pragma unroll
                for (int k = 16; k > 0; k >>= 1)
                    v += __shfl_xor_sync(0xFFFFFFFFu, v, k);
                if (lane == 0) p_part[warp][r][m] = v;
            }
        }
    }
    __syncthreads();

    // softmax: one thread per row.  slot m: group g=m/5, idx i=m%5,
    // halves contributed by warps g and 2+g.
    if (tid < RPB) {
        float s[M_SLOTS];
        float mx = -1e30f;
        #pragma unroll
        for (int m = 0; m < M_SLOTS; m++) {
            const int g = m / MS_HALF, i = m % MS_HALF;
            s[m] = p_part[g][tid][i] + p_part[2 + g][tid][i];
            mx = fmaxf(mx, s[m]);
        }
        float sum = 0.0f;
        #pragma unroll
        for (int m = 0; m < M_SLOTS; m++) { s[m] = __expf(s[m] - mx); sum += s[m]; }
        float inv = 1.0f / sum;
        #pragma unroll
        for (int m = 0; m < M_SLOTS; m++) p_fin[tid][m] = s[m] * inv;
    }
    __syncthreads();

    // ------------- Phase 2: value (R14 structure: j-quarter, all slots) ----
    u64 q[RPB][M_SLOTS];
    #pragma unroll
    for (int r = 0; r < RPB; r++)
        #pragma unroll
        for (int m = 0; m < M_SLOTS; m++) {
            float pv = p_fin[r][m];
            q[r][m] = pack2(pv, pv);
        }

    double2* __restrict__ o0 = (double2*)(out + (size_t)(row0 + 0) * HW);
    double2* __restrict__ o1 = (double2*)(out + (size_t)(row0 + 1) * HW);
    double2* __restrict__ o2 = (double2*)(out + (size_t)(row0 + 2) * HW);
    double2* __restrict__ o3 = (double2*)(out + (size_t)(row0 + 3) * HW);

    const int jbeg2 = warp * QL + lane;
    const int jend2 = warp * QL + QL;
    for (int j = jbeg2; j < jend2; j += 32) {
        u64 a0a = 0ull, a0b = 0ull, a1a = 0ull, a1b = 0ull;
        u64 a2a = 0ull, a2b = 0ull, a3a = 0ull, a3b = 0ull;
        #pragma unroll
        for (int m = 0; m < M_SLOTS; m++) {
            double2 wd = __ldg(&mw[(size_t)m * HWV + j]);
            const u64 wa = d2u(wd.x), wb = d2u(wd.y);
            a0a = fma2(q[0][m], wa, a0a);  a0b = fma2(q[0][m], wb, a0b);
            a1a = fma2(q[1][m], wa, a1a);  a1b = fma2(q[1][m], wb, a1b);
            a2a = fma2(q[2][m], wa, a2a);  a2b = fma2(q[2][m], wb, a2b);
            a3a = fma2(q[3][m], wa, a3a);  a3b = fma2(q[3][m], wb, a3b);
        }
        double2 v0, v1, v2, v3;
        v0.x = u2d(a0a); v0.y = u2d(a0b);
        v1.x = u2d(a1a); v1.y = u2d(a1b);
        v2.x = u2d(a2a); v2.y = u2d(a2b);
        v3.x = u2d(a3a); v3.y = u2d(a3b);
        __stcs(o0 + j, v0);
        __stcs(o1 + j, v1);
        __stcs(o2 + j, v2);
        __stcs(o3 + j, v3);
    }
}

extern "C" void kernel_launch(void* const* d_in, const int* in_sizes, int n_in,
                              void* d_out, int out_size) {
    const float* x   = (const float*)d_in[0];   // [32,256,88,88]
    const float* mem = (const float*)d_in[1];   // [10,88,88]
    float* out = (float*)d_out;

    dim3 grid(ROWS / RPB);    // 2048 blocks
    memaug_fused<<<grid, NT>>>(x, mem, out);
}